// round 2
// baseline (speedup 1.0000x reference)
#include <cuda_runtime.h>

#define N_NODES 50000
#define E_RAW   800000
#define E_TOT   850000   // E_RAW + N_NODES self loops
#define IN_DIM  128
#define C1      256      // HEADS*HID
#define HEADS   4
#define EPS     1e-16f

// ---------------- scratch (device globals; no allocation allowed) ----------
__device__ __align__(16) float g_h1[N_NODES * C1];      // layer1 projected feats
__device__ __align__(16) float g_out1[N_NODES * C1];    // layer1 aggregation
__device__ __align__(16) float g_as1[N_NODES * HEADS];
__device__ __align__(16) float g_ad1[N_NODES * HEADS];
__device__ __align__(16) float g_e1[E_TOT * HEADS];
__device__ __align__(16) float g_emax1[N_NODES * HEADS];
__device__ __align__(16) float g_den1[N_NODES * HEADS];
__device__ int   g_src[E_TOT];
__device__ int   g_dst[E_TOT];
__device__ float g_z[N_NODES];
__device__ float g_e2[E_TOT];
__device__ float g_emax2[N_NODES];
__device__ float g_den2[N_NODES];
__device__ float g_out2[N_NODES];
__device__ int   g_is64;   // 1 if edge_index buffer is int64, 0 if int32

// ---------------- helpers ---------------------------------------------------
__device__ __forceinline__ void atomicMaxF(float* addr, float v) {
    if (v >= 0.f) atomicMax((int*)addr, __float_as_int(v));
    else          atomicMin((unsigned int*)addr, __float_as_uint(v));
}

__device__ __forceinline__ float leaky(float v) {
    return v > 0.f ? v : 0.2f * v;
}

__device__ __forceinline__ int clampN(int v) {
    v = v < 0 ? 0 : v;
    return v >= N_NODES ? N_NODES - 1 : v;
}

// ---------------- kernels ---------------------------------------------------

// Detect whether the edge_index buffer holds int64 or int32 values.
// If int64 little-endian with values < 2^31, every odd 32-bit word is 0.
__global__ void k_detect(const int* __restrict__ ei32) {
    __shared__ int ok;
    if (threadIdx.x == 0) ok = 1;
    __syncthreads();
    // inspect first 1024 candidate int64 entries
    for (int i = threadIdx.x; i < 1024; i += blockDim.x) {
        if (ei32[2 * i + 1] != 0) ok = 0;
    }
    __syncthreads();
    if (threadIdx.x == 0) g_is64 = ok;
}

// Convert edge_index to int32 SoA + materialize self loops.
__global__ void k_prep_edges(const void* __restrict__ eiv) {
    int e = blockIdx.x * 256 + threadIdx.x;
    if (e >= E_TOT) return;
    if (e < E_RAW) {
        int s, d;
        if (g_is64) {
            const long long* ei = (const long long*)eiv;
            s = (int)ei[e];
            d = (int)ei[E_RAW + e];
        } else {
            const int* ei = (const int*)eiv;
            s = ei[e];
            d = ei[E_RAW + e];
        }
        g_src[e] = clampN(s);
        g_dst[e] = clampN(d);
    } else {
        int n = e - E_RAW;
        g_src[e] = n;
        g_dst[e] = n;
    }
}

// Zero / -inf init of all accumulators.
__global__ void k_init() {
    int i = blockIdx.x * 256 + threadIdx.x;
    if (i < N_NODES * C1) g_out1[i] = 0.f;
    if (i < N_NODES * HEADS) {
        g_emax1[i] = -__int_as_float(0x7f800000); // -inf
        g_den1[i]  = 0.f;
    }
    if (i < N_NODES) {
        g_emax2[i] = -__int_as_float(0x7f800000);
        g_den2[i]  = 0.f;
        g_out2[i]  = 0.f;
    }
}

// h1 = x @ W1   (50000x128 @ 128x256), fp32 SIMT tiled GEMM.
// tile: 128 rows x 128 cols, 256 threads, 8x8 per thread.
__global__ void k_gemm1(const float* __restrict__ x, const float* __restrict__ W1) {
    __shared__ float xs[32][132];  // [k][row]
    __shared__ float ws[32][132];  // [k][col]
    const int tx = threadIdx.x % 16;
    const int ty = threadIdx.x / 16;
    const int row0 = blockIdx.x * 128;
    const int col0 = blockIdx.y * 128;

    float acc[8][8];
#pragma unroll
    for (int i = 0; i < 8; i++)
#pragma unroll
        for (int j = 0; j < 8; j++) acc[i][j] = 0.f;

    for (int k0 = 0; k0 < IN_DIM; k0 += 32) {
        for (int i = threadIdx.x; i < 128 * 32; i += 256) {
            int r = i / 32, kk = i % 32;
            int row = row0 + r;
            xs[kk][r] = (row < N_NODES) ? x[row * IN_DIM + k0 + kk] : 0.f;
        }
        for (int i = threadIdx.x; i < 32 * 128; i += 256) {
            int kk = i / 128, cc = i % 128;
            ws[kk][cc] = W1[(k0 + kk) * C1 + col0 + cc];
        }
        __syncthreads();
#pragma unroll
        for (int kk = 0; kk < 32; kk++) {
            float xr[8], wr[8];
#pragma unroll
            for (int i = 0; i < 8; i++) xr[i] = xs[kk][ty * 8 + i];
#pragma unroll
            for (int j = 0; j < 8; j++) wr[j] = ws[kk][tx * 8 + j];
#pragma unroll
            for (int i = 0; i < 8; i++)
#pragma unroll
                for (int j = 0; j < 8; j++) acc[i][j] += xr[i] * wr[j];
        }
        __syncthreads();
    }
#pragma unroll
    for (int i = 0; i < 8; i++) {
        int row = row0 + ty * 8 + i;
        if (row >= N_NODES) continue;
#pragma unroll
        for (int j = 0; j < 8; j++)
            g_h1[row * C1 + col0 + tx * 8 + j] = acc[i][j];
    }
}

// Per-(node,head) attention logits.
__global__ void k_alpha1(const float* __restrict__ a_src1,
                         const float* __restrict__ a_dst1) {
    int t = blockIdx.x * 256 + threadIdx.x;     // node*4 + head
    if (t >= N_NODES * HEADS) return;
    int n = t >> 2, h = t & 3;
    const float* hp = g_h1 + n * C1 + h * 64;
    float s = 0.f, d = 0.f;
#pragma unroll 8
    for (int k = 0; k < 64; k++) {
        float v = hp[k];
        s += v * a_src1[h * 64 + k];
        d += v * a_dst1[h * 64 + k];
    }
    g_as1[t] = s;
    g_ad1[t] = d;
}

// Edge pass A: per-edge score + segment max.
__global__ void k_edge1a() {
    int e = blockIdx.x * 256 + threadIdx.x;
    if (e >= E_TOT) return;
    int s = g_src[e], d = g_dst[e];
    float4 as = *(const float4*)(g_as1 + s * 4);
    float4 ad = *(const float4*)(g_ad1 + d * 4);
    float v0 = leaky(as.x + ad.x);
    float v1 = leaky(as.y + ad.y);
    float v2 = leaky(as.z + ad.z);
    float v3 = leaky(as.w + ad.w);
    *(float4*)(g_e1 + e * 4) = make_float4(v0, v1, v2, v3);
    atomicMaxF(&g_emax1[d * 4 + 0], v0);
    atomicMaxF(&g_emax1[d * 4 + 1], v1);
    atomicMaxF(&g_emax1[d * 4 + 2], v2);
    atomicMaxF(&g_emax1[d * 4 + 3], v3);
}

// Edge pass B: exp(e - max) + segment sum.
__global__ void k_edge1b() {
    int e = blockIdx.x * 256 + threadIdx.x;
    if (e >= E_TOT) return;
    int d = g_dst[e];
    float4 ev = *(const float4*)(g_e1 + e * 4);
    float4 m  = *(const float4*)(g_emax1 + d * 4);
    float w0 = expf(ev.x - m.x);
    float w1 = expf(ev.y - m.y);
    float w2 = expf(ev.z - m.z);
    float w3 = expf(ev.w - m.w);
    *(float4*)(g_e1 + e * 4) = make_float4(w0, w1, w2, w3);
    atomicAdd(&g_den1[d * 4 + 0], w0);
    atomicAdd(&g_den1[d * 4 + 1], w1);
    atomicAdd(&g_den1[d * 4 + 2], w2);
    atomicAdd(&g_den1[d * 4 + 3], w3);
}

// Edge pass C: weighted scatter-aggregate. One warp per edge; each lane moves
// two float4 (8 floats) of the 256-float message with vector atomics.
__global__ void k_edge1c() {
    int gtid = blockIdx.x * 256 + threadIdx.x;
    int e    = gtid >> 5;
    int lane = gtid & 31;
    if (e >= E_TOT) return;
    int s = g_src[e], d = g_dst[e];
    int h = lane >> 3;
    float alpha = g_e1[e * 4 + h] / (g_den1[d * 4 + h] + EPS);
    const float4* hs = (const float4*)(g_h1 + (long)s * C1);
    float4* od = (float4*)(g_out1 + (long)d * C1);
    float4 v0 = hs[lane * 2];
    float4 v1 = hs[lane * 2 + 1];
    v0.x *= alpha; v0.y *= alpha; v0.z *= alpha; v0.w *= alpha;
    v1.x *= alpha; v1.y *= alpha; v1.z *= alpha; v1.w *= alpha;
    atomicAdd(od + lane * 2,     v0);
    atomicAdd(od + lane * 2 + 1, v1);
}

// hidden = relu(out1 + b1); z = hidden @ W2. One warp per node.
__global__ void k_z(const float* __restrict__ b1, const float* __restrict__ W2) {
    int gtid = blockIdx.x * 256 + threadIdx.x;
    int n    = gtid >> 5;
    int lane = gtid & 31;
    if (n >= N_NODES) return;
    float sum = 0.f;
#pragma unroll
    for (int j = 0; j < 8; j++) {
        int c = j * 32 + lane;
        float v = g_out1[(long)n * C1 + c] + b1[c];
        v = fmaxf(v, 0.f);
        sum += v * W2[c];
    }
#pragma unroll
    for (int o = 16; o; o >>= 1) sum += __shfl_xor_sync(0xffffffffu, sum, o);
    if (lane == 0) g_z[n] = sum;
}

__global__ void k_edge2a(const float* __restrict__ a_src2,
                         const float* __restrict__ a_dst2) {
    int e = blockIdx.x * 256 + threadIdx.x;
    if (e >= E_TOT) return;
    int s = g_src[e], d = g_dst[e];
    float v = leaky(g_z[s] * a_src2[0] + g_z[d] * a_dst2[0]);
    g_e2[e] = v;
    atomicMaxF(&g_emax2[d], v);
}

__global__ void k_edge2b() {
    int e = blockIdx.x * 256 + threadIdx.x;
    if (e >= E_TOT) return;
    int d = g_dst[e];
    float w = expf(g_e2[e] - g_emax2[d]);
    g_e2[e] = w;
    atomicAdd(&g_den2[d], w);
}

__global__ void k_edge2c() {
    int e = blockIdx.x * 256 + threadIdx.x;
    if (e >= E_TOT) return;
    int s = g_src[e], d = g_dst[e];
    float alpha = g_e2[e] / (g_den2[d] + EPS);
    atomicAdd(&g_out2[d], g_z[s] * alpha);
}

__global__ void k_final(float* __restrict__ out, const float* __restrict__ b2) {
    int n = blockIdx.x * 256 + threadIdx.x;
    if (n >= N_NODES) return;
    float v = g_out2[n] + b2[0];
    out[n] = 1.f / (1.f + expf(-v));
}

// ---------------- launch ----------------------------------------------------
extern "C" void kernel_launch(void* const* d_in, const int* in_sizes, int n_in,
                              void* d_out, int out_size) {
    const float* x      = (const float*)d_in[0];
    const void*  ei     = d_in[1];
    const float* W1     = (const float*)d_in[2];
    const float* a_src1 = (const float*)d_in[3];
    const float* a_dst1 = (const float*)d_in[4];
    const float* b1     = (const float*)d_in[5];
    const float* W2     = (const float*)d_in[6];
    const float* a_src2 = (const float*)d_in[7];
    const float* a_dst2 = (const float*)d_in[8];
    const float* b2     = (const float*)d_in[9];
    float*       out    = (float*)d_out;

    const int TB = 256;
    int eb  = (E_TOT + TB - 1) / TB;
    int ib  = (N_NODES * C1 + TB - 1) / TB;
    int ab  = (N_NODES * HEADS + TB - 1) / TB;
    int e1c = (E_TOT * 32 + TB - 1) / TB;
    int zb  = (N_NODES * 32 + TB - 1) / TB;
    int nb  = (N_NODES + TB - 1) / TB;

    k_detect<<<1, 256>>>((const int*)ei);
    k_prep_edges<<<eb, TB>>>(ei);
    k_init<<<ib, TB>>>();
    {
        dim3 grid((N_NODES + 127) / 128, C1 / 128);
        k_gemm1<<<grid, TB>>>(x, W1);
    }
    k_alpha1<<<ab, TB>>>(a_src1, a_dst1);
    k_edge1a<<<eb, TB>>>();
    k_edge1b<<<eb, TB>>>();
    k_edge1c<<<e1c, TB>>>();
    k_z<<<zb, TB>>>(b1, W2);
    k_edge2a<<<eb, TB>>>(a_src2, a_dst2);
    k_edge2b<<<eb, TB>>>();
    k_edge2c<<<eb, TB>>>();
    k_final<<<nb, TB>>>(out, b2);
}

// round 3
// speedup vs baseline: 1.5980x; 1.5980x over previous
#include <cuda_runtime.h>

#define N_NODES 50000
#define E_RAW   800000
#define E_TOT   850000   // E_RAW + N_NODES self loops
#define IN_DIM  128
#define C1      256      // HEADS*HID
#define HEADS   4
#define EPS     1e-16f
#define NEG_INF (-__int_as_float(0x7f800000))

// ---------------- scratch (device globals; no allocation allowed) ----------
__device__ __align__(16) float g_h1[N_NODES * C1];      // layer1 projected feats
__device__ __align__(16) float g_as1[N_NODES * HEADS];
__device__ __align__(16) float g_ad1[N_NODES * HEADS];
__device__ __align__(16) float g_e1[E_TOT * HEADS];     // per-slot scores (sorted order)
__device__ int   g_src[E_TOT];     // unsorted
__device__ int   g_dst[E_TOT];
__device__ int   g_ssrc[E_TOT];    // dst-sorted src
__device__ int   g_sdst[E_TOT];    // dst-sorted dst
__device__ int   g_deg[N_NODES];
__device__ int   g_cur[N_NODES];
__device__ int   g_off[N_NODES + 1];
__device__ float g_z[N_NODES];
__device__ int   g_is64;

// ---------------- helpers ---------------------------------------------------
__device__ __forceinline__ float leaky(float v) { return v > 0.f ? v : 0.2f * v; }
__device__ __forceinline__ int clampN(int v) {
    v = v < 0 ? 0 : v;
    return v >= N_NODES ? N_NODES - 1 : v;
}

// ---------------- edge prep -------------------------------------------------
__global__ void k_detect(const int* __restrict__ ei32) {
    __shared__ int ok;
    if (threadIdx.x == 0) ok = 1;
    __syncthreads();
    for (int i = threadIdx.x; i < 1024; i += blockDim.x)
        if (ei32[2 * i + 1] != 0) ok = 0;
    __syncthreads();
    if (threadIdx.x == 0) g_is64 = ok;
}

__global__ void k_prep_edges(const void* __restrict__ eiv) {
    int e = blockIdx.x * 256 + threadIdx.x;
    if (e >= E_TOT) return;
    if (e < E_RAW) {
        int s, d;
        if (g_is64) {
            const long long* ei = (const long long*)eiv;
            s = (int)ei[e];
            d = (int)ei[E_RAW + e];
        } else {
            const int* ei = (const int*)eiv;
            s = ei[e];
            d = ei[E_RAW + e];
        }
        g_src[e] = clampN(s);
        g_dst[e] = clampN(d);
    } else {
        int n = e - E_RAW;
        g_src[e] = n;
        g_dst[e] = n;
    }
}

__global__ void k_init() {
    int i = blockIdx.x * 256 + threadIdx.x;
    if (i < N_NODES) { g_deg[i] = 0; g_cur[i] = 0; }
}

__global__ void k_hist() {
    int e = blockIdx.x * 256 + threadIdx.x;
    if (e >= E_TOT) return;
    atomicAdd(&g_deg[g_dst[e]], 1);
}

// Single-block exclusive scan over 50k degrees.
__global__ void k_scan() {
    __shared__ int part[1024];
    const int CH = (N_NODES + 1023) / 1024;   // 49
    int t = threadIdx.x;
    int beg = t * CH;
    int fin = beg + CH; if (fin > N_NODES) fin = N_NODES;
    int s = 0;
    for (int i = beg; i < fin; i++) s += g_deg[i];
    part[t] = s;
    __syncthreads();
    for (int o = 1; o < 1024; o <<= 1) {
        int v = (t >= o) ? part[t - o] : 0;
        __syncthreads();
        part[t] += v;
        __syncthreads();
    }
    int ex = (t == 0) ? 0 : part[t - 1];
    for (int i = beg; i < fin; i++) { g_off[i] = ex; ex += g_deg[i]; }
    if (t == 1023) g_off[N_NODES] = part[1023];
}

__global__ void k_scatter() {
    int e = blockIdx.x * 256 + threadIdx.x;
    if (e >= E_TOT) return;
    int d = g_dst[e];
    int slot = g_off[d] + atomicAdd(&g_cur[d], 1);
    g_ssrc[slot] = g_src[e];
    g_sdst[slot] = d;
}

// ---------------- layer 1 ----------------------------------------------------

// h1 = x @ W1   (50000x128 @ 128x256), fp32 SIMT tiled GEMM.
__global__ void k_gemm1(const float* __restrict__ x, const float* __restrict__ W1) {
    __shared__ float xs[32][132];
    __shared__ float ws[32][132];
    const int tx = threadIdx.x % 16;
    const int ty = threadIdx.x / 16;
    const int row0 = blockIdx.x * 128;
    const int col0 = blockIdx.y * 128;

    float acc[8][8];
#pragma unroll
    for (int i = 0; i < 8; i++)
#pragma unroll
        for (int j = 0; j < 8; j++) acc[i][j] = 0.f;

    for (int k0 = 0; k0 < IN_DIM; k0 += 32) {
        for (int i = threadIdx.x; i < 128 * 32; i += 256) {
            int r = i / 32, kk = i % 32;
            int row = row0 + r;
            xs[kk][r] = (row < N_NODES) ? x[row * IN_DIM + k0 + kk] : 0.f;
        }
        for (int i = threadIdx.x; i < 32 * 128; i += 256) {
            int kk = i / 128, cc = i % 128;
            ws[kk][cc] = W1[(k0 + kk) * C1 + col0 + cc];
        }
        __syncthreads();
#pragma unroll
        for (int kk = 0; kk < 32; kk++) {
            float xr[8], wr[8];
#pragma unroll
            for (int i = 0; i < 8; i++) xr[i] = xs[kk][ty * 8 + i];
#pragma unroll
            for (int j = 0; j < 8; j++) wr[j] = ws[kk][tx * 8 + j];
#pragma unroll
            for (int i = 0; i < 8; i++)
#pragma unroll
                for (int j = 0; j < 8; j++) acc[i][j] += xr[i] * wr[j];
        }
        __syncthreads();
    }
#pragma unroll
    for (int i = 0; i < 8; i++) {
        int row = row0 + ty * 8 + i;
        if (row >= N_NODES) continue;
#pragma unroll
        for (int j = 0; j < 8; j++)
            g_h1[row * C1 + col0 + tx * 8 + j] = acc[i][j];
    }
}

// Per-(node,head) attention logits.
__global__ void k_alpha1(const float* __restrict__ a_src1,
                         const float* __restrict__ a_dst1) {
    int t = blockIdx.x * 256 + threadIdx.x;
    if (t >= N_NODES * HEADS) return;
    int n = t >> 2, h = t & 3;
    const float* hp = g_h1 + n * C1 + h * 64;
    float s = 0.f, d = 0.f;
#pragma unroll 8
    for (int k = 0; k < 64; k++) {
        float v = hp[k];
        s += v * a_src1[h * 64 + k];
        d += v * a_dst1[h * 64 + k];
    }
    g_as1[t] = s;
    g_ad1[t] = d;
}

// Per-slot (dst-sorted) leaky scores, no atomics.
__global__ void k_score1() {
    int t = blockIdx.x * 256 + threadIdx.x;
    if (t >= E_TOT) return;
    int s = g_ssrc[t], d = g_sdst[t];
    float4 as = *(const float4*)(g_as1 + s * 4);
    float4 ad = *(const float4*)(g_ad1 + d * 4);
    float4 r;
    r.x = leaky(as.x + ad.x);
    r.y = leaky(as.y + ad.y);
    r.z = leaky(as.z + ad.z);
    r.w = leaky(as.w + ad.w);
    *(float4*)(g_e1 + t * 4) = r;
}

// Fused per-node: segment softmax + weighted aggregate + relu + bias + W2 dot.
// One warp per node; lane owns 8 output columns (head = lane/8). Writes g_z[n].
__global__ void k_agg1(const float* __restrict__ b1, const float* __restrict__ W2) {
    int gtid = blockIdx.x * 256 + threadIdx.x;
    int n    = gtid >> 5;
    int lane = gtid & 31;
    if (n >= N_NODES) return;
    int base = g_off[n];
    int end  = g_off[n + 1];
    int head = lane >> 3;

    // pass 1: per-head max (lane-strided over edges, warp reduce)
    float m0 = NEG_INF, m1 = NEG_INF, m2 = NEG_INF, m3 = NEG_INF;
    for (int t = base + lane; t < end; t += 32) {
        float4 ev = *(const float4*)(g_e1 + t * 4);
        m0 = fmaxf(m0, ev.x); m1 = fmaxf(m1, ev.y);
        m2 = fmaxf(m2, ev.z); m3 = fmaxf(m3, ev.w);
    }
#pragma unroll
    for (int o = 16; o; o >>= 1) {
        m0 = fmaxf(m0, __shfl_xor_sync(0xffffffffu, m0, o));
        m1 = fmaxf(m1, __shfl_xor_sync(0xffffffffu, m1, o));
        m2 = fmaxf(m2, __shfl_xor_sync(0xffffffffu, m2, o));
        m3 = fmaxf(m3, __shfl_xor_sync(0xffffffffu, m3, o));
    }

    // pass 2: per-head denom
    float d0 = 0.f, d1 = 0.f, d2 = 0.f, d3 = 0.f;
    for (int t = base + lane; t < end; t += 32) {
        float4 ev = *(const float4*)(g_e1 + t * 4);
        d0 += expf(ev.x - m0); d1 += expf(ev.y - m1);
        d2 += expf(ev.z - m2); d3 += expf(ev.w - m3);
    }
#pragma unroll
    for (int o = 16; o; o >>= 1) {
        d0 += __shfl_xor_sync(0xffffffffu, d0, o);
        d1 += __shfl_xor_sync(0xffffffffu, d1, o);
        d2 += __shfl_xor_sync(0xffffffffu, d2, o);
        d3 += __shfl_xor_sync(0xffffffffu, d3, o);
    }

    float mh  = (head == 0) ? m0 : (head == 1) ? m1 : (head == 2) ? m2 : m3;
    float dh  = (head == 0) ? d0 : (head == 1) ? d1 : (head == 2) ? d2 : d3;
    float inv = 1.f / (dh + EPS);

    // pass 3: weighted gather-aggregate (warp walks edges together; lane owns 8 cols)
    int c0 = lane * 8;
    float4 a0 = make_float4(0.f, 0.f, 0.f, 0.f);
    float4 a1 = make_float4(0.f, 0.f, 0.f, 0.f);
    for (int t = base; t < end; t++) {
        int s = g_ssrc[t];
        float w = expf(g_e1[t * 4 + head] - mh) * inv;   // broadcast load per 8 lanes
        const float4* hp = (const float4*)(g_h1 + s * C1 + c0);
        float4 v0 = hp[0];
        float4 v1 = hp[1];
        a0.x += w * v0.x; a0.y += w * v0.y; a0.z += w * v0.z; a0.w += w * v0.w;
        a1.x += w * v1.x; a1.y += w * v1.y; a1.z += w * v1.z; a1.w += w * v1.w;
    }

    // epilogue: relu(out + b1) . W2  -> g_z[n]
    float4 bb0 = *(const float4*)(b1 + c0);
    float4 bb1 = *(const float4*)(b1 + c0 + 4);
    float4 w0  = *(const float4*)(W2 + c0);
    float4 w1  = *(const float4*)(W2 + c0 + 4);
    float p = 0.f;
    p += fmaxf(a0.x + bb0.x, 0.f) * w0.x;
    p += fmaxf(a0.y + bb0.y, 0.f) * w0.y;
    p += fmaxf(a0.z + bb0.z, 0.f) * w0.z;
    p += fmaxf(a0.w + bb0.w, 0.f) * w0.w;
    p += fmaxf(a1.x + bb1.x, 0.f) * w1.x;
    p += fmaxf(a1.y + bb1.y, 0.f) * w1.y;
    p += fmaxf(a1.z + bb1.z, 0.f) * w1.z;
    p += fmaxf(a1.w + bb1.w, 0.f) * w1.w;
#pragma unroll
    for (int o = 16; o; o >>= 1) p += __shfl_xor_sync(0xffffffffu, p, o);
    if (lane == 0) g_z[n] = p;
}

// ---------------- layer 2 (fully fused, warp per node) -----------------------
__global__ void k_layer2(float* __restrict__ out,
                         const float* __restrict__ a_src2,
                         const float* __restrict__ a_dst2,
                         const float* __restrict__ b2) {
    int gtid = blockIdx.x * 256 + threadIdx.x;
    int n    = gtid >> 5;
    int lane = gtid & 31;
    if (n >= N_NODES) return;
    float asc = a_src2[0];
    float zd  = g_z[n] * a_dst2[0];
    int base = g_off[n];
    int end  = g_off[n + 1];

    float m = NEG_INF;
    for (int t = base + lane; t < end; t += 32)
        m = fmaxf(m, leaky(g_z[g_ssrc[t]] * asc + zd));
#pragma unroll
    for (int o = 16; o; o >>= 1) m = fmaxf(m, __shfl_xor_sync(0xffffffffu, m, o));

    float num = 0.f, den = 0.f;
    for (int t = base + lane; t < end; t += 32) {
        float zs = g_z[g_ssrc[t]];
        float w = expf(leaky(zs * asc + zd) - m);
        num += w * zs;
        den += w;
    }
#pragma unroll
    for (int o = 16; o; o >>= 1) {
        num += __shfl_xor_sync(0xffffffffu, num, o);
        den += __shfl_xor_sync(0xffffffffu, den, o);
    }
    if (lane == 0) {
        float v = num / (den + EPS) + b2[0];
        out[n] = 1.f / (1.f + expf(-v));
    }
}

// ---------------- launch ----------------------------------------------------
extern "C" void kernel_launch(void* const* d_in, const int* in_sizes, int n_in,
                              void* d_out, int out_size) {
    const float* x      = (const float*)d_in[0];
    const void*  ei     = d_in[1];
    const float* W1     = (const float*)d_in[2];
    const float* a_src1 = (const float*)d_in[3];
    const float* a_dst1 = (const float*)d_in[4];
    const float* b1     = (const float*)d_in[5];
    const float* W2     = (const float*)d_in[6];
    const float* a_src2 = (const float*)d_in[7];
    const float* a_dst2 = (const float*)d_in[8];
    const float* b2     = (const float*)d_in[9];
    float*       out    = (float*)d_out;

    const int TB = 256;
    int eb = (E_TOT + TB - 1) / TB;
    int ab = (N_NODES * HEADS + TB - 1) / TB;
    int wb = (N_NODES * 32 + TB - 1) / TB;   // warp-per-node blocks
    int nb = (N_NODES + TB - 1) / TB;

    k_detect<<<1, 256>>>((const int*)ei);
    k_prep_edges<<<eb, TB>>>(ei);
    k_init<<<nb, TB>>>();
    k_hist<<<eb, TB>>>();
    k_scan<<<1, 1024>>>();
    k_scatter<<<eb, TB>>>();
    {
        dim3 grid((N_NODES + 127) / 128, C1 / 128);
        k_gemm1<<<grid, TB>>>(x, W1);
    }
    k_alpha1<<<ab, TB>>>(a_src1, a_dst1);
    k_score1<<<eb, TB>>>();
    k_agg1<<<wb, TB>>>(b1, W2);
    k_layer2<<<wb, TB>>>(out, a_src2, a_dst2, b2);
}

// round 4
// speedup vs baseline: 1.8011x; 1.1270x over previous
#include <cuda_runtime.h>

#define N_NODES 50000
#define E_RAW   800000
#define E_TOT   850000   // E_RAW + N_NODES self loops
#define IN_DIM  128
#define C1      256      // HEADS*HID
#define HEADS   4
#define EPS     1e-16f

// ---------------- scratch (device globals; no allocation allowed) ----------
__device__ __align__(16) float g_h1[N_NODES * C1];
__device__ __align__(16) float g_as1[N_NODES * HEADS];
__device__ __align__(16) float g_ad1[N_NODES * HEADS];
__device__ int   g_src[E_TOT];
__device__ int   g_dst[E_TOT];
__device__ int   g_ssrc[E_TOT];    // dst-sorted src
__device__ int   g_deg[N_NODES];
__device__ int   g_cur[N_NODES];
__device__ int   g_off[N_NODES + 1];
__device__ float g_z[N_NODES];
__device__ int   g_is64;

// ---------------- helpers ---------------------------------------------------
__device__ __forceinline__ float leaky(float v) { return v > 0.f ? v : 0.2f * v; }
__device__ __forceinline__ int clampN(int v) {
    v = v < 0 ? 0 : v;
    return v >= N_NODES ? N_NODES - 1 : v;
}
__device__ __forceinline__ void cp_async16(void* sdst, const void* gsrc, int nbytes) {
    unsigned u = (unsigned)__cvta_generic_to_shared(sdst);
    asm volatile("cp.async.cg.shared.global [%0], [%1], 16, %2;\n"
                 :: "r"(u), "l"(gsrc), "r"(nbytes));
}

// ---------------- edge prep -------------------------------------------------
// init degree/cursor + dtype detection (block 0)
__global__ void k_init(const int* __restrict__ ei32) {
    int i = blockIdx.x * 256 + threadIdx.x;
    if (i < N_NODES) { g_deg[i] = 0; g_cur[i] = 0; }
    if (blockIdx.x == 0) {
        __shared__ int ok;
        if (threadIdx.x == 0) ok = 1;
        __syncthreads();
        for (int j = threadIdx.x; j < 1024; j += 256)
            if (ei32[2 * j + 1] != 0) ok = 0;
        __syncthreads();
        if (threadIdx.x == 0) g_is64 = ok;
    }
}

// decode edges + histogram in one pass
__global__ void k_prep(const void* __restrict__ eiv) {
    int e = blockIdx.x * 256 + threadIdx.x;
    if (e >= E_TOT) return;
    int s, d;
    if (e < E_RAW) {
        if (g_is64) {
            const long long* ei = (const long long*)eiv;
            s = (int)ei[e];
            d = (int)ei[E_RAW + e];
        } else {
            const int* ei = (const int*)eiv;
            s = ei[e];
            d = ei[E_RAW + e];
        }
        s = clampN(s); d = clampN(d);
    } else {
        s = d = e - E_RAW;
    }
    g_src[e] = s;
    g_dst[e] = d;
    atomicAdd(&g_deg[d], 1);
}

// Single-block exclusive scan over 50k degrees.
__global__ void k_scan() {
    __shared__ int part[1024];
    const int CH = (N_NODES + 1023) / 1024;
    int t = threadIdx.x;
    int beg = t * CH;
    int fin = beg + CH; if (fin > N_NODES) fin = N_NODES;
    int s = 0;
    for (int i = beg; i < fin; i++) s += g_deg[i];
    part[t] = s;
    __syncthreads();
    for (int o = 1; o < 1024; o <<= 1) {
        int v = (t >= o) ? part[t - o] : 0;
        __syncthreads();
        part[t] += v;
        __syncthreads();
    }
    int ex = (t == 0) ? 0 : part[t - 1];
    for (int i = beg; i < fin; i++) { g_off[i] = ex; ex += g_deg[i]; }
    if (t == 1023) g_off[N_NODES] = part[1023];
}

__global__ void k_scatter() {
    int e = blockIdx.x * 256 + threadIdx.x;
    if (e >= E_TOT) return;
    int d = g_dst[e];
    int slot = g_off[d] + atomicAdd(&g_cur[d], 1);
    g_ssrc[slot] = g_src[e];
}

// ---------------- layer 1 ----------------------------------------------------

// h1 = x @ W1  (50000x128 @ 128x256). cp.async double-buffered, 128x128 tile.
#define KT 16
__global__ __launch_bounds__(256) void k_gemm1(const float* __restrict__ x,
                                               const float* __restrict__ W1) {
    __shared__ float xs[2][128][20];   // [buf][row][k] pad 20 (80B rows, 16B aligned)
    __shared__ float ws[2][KT][132];   // [buf][k][col]
    const int tid = threadIdx.x;
    const int tx = tid & 15;
    const int ty = tid >> 4;
    const int row0 = blockIdx.x * 128;
    const int col0 = blockIdx.y * 128;

    float acc[8][8];
#pragma unroll
    for (int i = 0; i < 8; i++)
#pragma unroll
        for (int j = 0; j < 8; j++) acc[i][j] = 0.f;

#define LOAD_TILE(KTIL, B)                                                      \
    do {                                                                        \
        int base = (KTIL) * KT;                                                 \
        _Pragma("unroll")                                                       \
        for (int c = 0; c < 2; c++) {                                           \
            int idx = tid + 256 * c;             /* 0..511 */                   \
            int r = idx >> 2, kc = idx & 3;                                     \
            int row = row0 + r;                                                 \
            cp_async16(&xs[B][r][kc * 4],                                       \
                       x + (size_t)row * IN_DIM + base + kc * 4,                \
                       row < N_NODES ? 16 : 0);                                 \
        }                                                                       \
        _Pragma("unroll")                                                       \
        for (int c = 0; c < 2; c++) {                                           \
            int idx = tid + 256 * c;                                            \
            int kk = idx >> 5, cc = idx & 31;                                   \
            cp_async16(&ws[B][kk][cc * 4],                                      \
                       W1 + (size_t)(base + kk) * C1 + col0 + cc * 4, 16);      \
        }                                                                       \
        asm volatile("cp.async.commit_group;\n");                               \
    } while (0)

    LOAD_TILE(0, 0);
    const int NKT = IN_DIM / KT;   // 8
    for (int kt = 0; kt < NKT; kt++) {
        int b = kt & 1;
        if (kt + 1 < NKT) {
            LOAD_TILE(kt + 1, b ^ 1);
            asm volatile("cp.async.wait_group 1;\n");
        } else {
            asm volatile("cp.async.wait_group 0;\n");
        }
        __syncthreads();
#pragma unroll
        for (int kk = 0; kk < KT; kk++) {
            float4 w0 = *(const float4*)&ws[b][kk][tx * 8];
            float4 w1 = *(const float4*)&ws[b][kk][tx * 8 + 4];
            float xr[8];
#pragma unroll
            for (int i = 0; i < 8; i++) xr[i] = xs[b][ty * 8 + i][kk];
#pragma unroll
            for (int i = 0; i < 8; i++) {
                acc[i][0] += xr[i] * w0.x;
                acc[i][1] += xr[i] * w0.y;
                acc[i][2] += xr[i] * w0.z;
                acc[i][3] += xr[i] * w0.w;
                acc[i][4] += xr[i] * w1.x;
                acc[i][5] += xr[i] * w1.y;
                acc[i][6] += xr[i] * w1.z;
                acc[i][7] += xr[i] * w1.w;
            }
        }
        __syncthreads();   // protect buf b from next-next prefetch
    }
#pragma unroll
    for (int i = 0; i < 8; i++) {
        int row = row0 + ty * 8 + i;
        if (row >= N_NODES) continue;
#pragma unroll
        for (int j = 0; j < 8; j += 4)
            *(float4*)&g_h1[(size_t)row * C1 + col0 + tx * 8 + j] =
                make_float4(acc[i][j], acc[i][j + 1], acc[i][j + 2], acc[i][j + 3]);
    }
#undef LOAD_TILE
}

// Per-(node,head) attention logits, vectorized.
__global__ void k_alpha1(const float* __restrict__ a_src1,
                         const float* __restrict__ a_dst1) {
    int t = blockIdx.x * 256 + threadIdx.x;
    if (t >= N_NODES * HEADS) return;
    int n = t >> 2, h = t & 3;
    const float4* hp  = (const float4*)(g_h1 + (size_t)n * C1 + h * 64);
    const float4* ap  = (const float4*)(a_src1 + h * 64);
    const float4* bp  = (const float4*)(a_dst1 + h * 64);
    float s = 0.f, d = 0.f;
#pragma unroll
    for (int k = 0; k < 16; k++) {
        float4 v = hp[k], a = ap[k], b = bp[k];
        s += v.x * a.x + v.y * a.y + v.z * a.z + v.w * a.w;
        d += v.x * b.x + v.y * b.y + v.z * b.z + v.w * b.w;
    }
    g_as1[t] = s;
    g_ad1[t] = d;
}

// Fused per-node: online segment softmax + weighted aggregate + relu+bias+W2.
// One warp per node; lane owns 8 output cols (head = lane/8). Writes g_z[n].
__global__ void k_agg1(const float* __restrict__ b1, const float* __restrict__ W2) {
    int gtid = blockIdx.x * 256 + threadIdx.x;
    int n    = gtid >> 5;
    int lane = gtid & 31;
    if (n >= N_NODES) return;
    int base = g_off[n];
    int end  = g_off[n + 1];
    int head = lane >> 3;
    float4 ad4 = *(const float4*)(g_ad1 + n * 4);

    // pass 1: online max+denom per head (lane-strided, then warp combine)
    float m0 = -1e30f, m1 = -1e30f, m2 = -1e30f, m3 = -1e30f;
    float d0 = 0.f, d1 = 0.f, d2 = 0.f, d3 = 0.f;
    for (int t = base + lane; t < end; t += 32) {
        int s = g_ssrc[t];
        float4 as = *(const float4*)(g_as1 + s * 4);
        float v0 = leaky(as.x + ad4.x);
        float v1 = leaky(as.y + ad4.y);
        float v2 = leaky(as.z + ad4.z);
        float v3 = leaky(as.w + ad4.w);
        float nm;
        nm = fmaxf(m0, v0); d0 = d0 * expf(m0 - nm) + expf(v0 - nm); m0 = nm;
        nm = fmaxf(m1, v1); d1 = d1 * expf(m1 - nm) + expf(v1 - nm); m1 = nm;
        nm = fmaxf(m2, v2); d2 = d2 * expf(m2 - nm) + expf(v2 - nm); m2 = nm;
        nm = fmaxf(m3, v3); d3 = d3 * expf(m3 - nm) + expf(v3 - nm); m3 = nm;
    }
#pragma unroll
    for (int o = 16; o; o >>= 1) {
        float mo, dd, nm;
        mo = __shfl_xor_sync(0xffffffffu, m0, o); dd = __shfl_xor_sync(0xffffffffu, d0, o);
        nm = fmaxf(m0, mo); d0 = d0 * expf(m0 - nm) + dd * expf(mo - nm); m0 = nm;
        mo = __shfl_xor_sync(0xffffffffu, m1, o); dd = __shfl_xor_sync(0xffffffffu, d1, o);
        nm = fmaxf(m1, mo); d1 = d1 * expf(m1 - nm) + dd * expf(mo - nm); m1 = nm;
        mo = __shfl_xor_sync(0xffffffffu, m2, o); dd = __shfl_xor_sync(0xffffffffu, d2, o);
        nm = fmaxf(m2, mo); d2 = d2 * expf(m2 - nm) + dd * expf(mo - nm); m2 = nm;
        mo = __shfl_xor_sync(0xffffffffu, m3, o); dd = __shfl_xor_sync(0xffffffffu, d3, o);
        nm = fmaxf(m3, mo); d3 = d3 * expf(m3 - nm) + dd * expf(mo - nm); m3 = nm;
    }

    float mh  = (head == 0) ? m0 : (head == 1) ? m1 : (head == 2) ? m2 : m3;
    float dh  = (head == 0) ? d0 : (head == 1) ? d1 : (head == 2) ? d2 : d3;
    float adh = (head == 0) ? ad4.x : (head == 1) ? ad4.y : (head == 2) ? ad4.z : ad4.w;
    float inv = 1.f / (dh + EPS);

    // pass 2: weighted gather-aggregate (warp walks edges; lane owns 8 cols)
    int c0 = lane * 8;
    float4 a0 = make_float4(0.f, 0.f, 0.f, 0.f);
    float4 a1 = make_float4(0.f, 0.f, 0.f, 0.f);
    for (int t = base; t < end; t++) {
        int s = g_ssrc[t];                                     // broadcast
        float w = expf(leaky(g_as1[s * 4 + head] + adh) - mh) * inv;
        const float4* hp = (const float4*)(g_h1 + (size_t)s * C1 + c0);
        float4 v0 = hp[0];
        float4 v1 = hp[1];
        a0.x += w * v0.x; a0.y += w * v0.y; a0.z += w * v0.z; a0.w += w * v0.w;
        a1.x += w * v1.x; a1.y += w * v1.y; a1.z += w * v1.z; a1.w += w * v1.w;
    }

    // epilogue: relu(out + b1) . W2 -> g_z[n]
    float4 bb0 = *(const float4*)(b1 + c0);
    float4 bb1 = *(const float4*)(b1 + c0 + 4);
    float4 w0  = *(const float4*)(W2 + c0);
    float4 w1  = *(const float4*)(W2 + c0 + 4);
    float p = 0.f;
    p += fmaxf(a0.x + bb0.x, 0.f) * w0.x;
    p += fmaxf(a0.y + bb0.y, 0.f) * w0.y;
    p += fmaxf(a0.z + bb0.z, 0.f) * w0.z;
    p += fmaxf(a0.w + bb0.w, 0.f) * w0.w;
    p += fmaxf(a1.x + bb1.x, 0.f) * w1.x;
    p += fmaxf(a1.y + bb1.y, 0.f) * w1.y;
    p += fmaxf(a1.z + bb1.z, 0.f) * w1.z;
    p += fmaxf(a1.w + bb1.w, 0.f) * w1.w;
#pragma unroll
    for (int o = 16; o; o >>= 1) p += __shfl_xor_sync(0xffffffffu, p, o);
    if (lane == 0) g_z[n] = p;
}

// ---------------- layer 2 (fused, warp per node, online softmax) -------------
__global__ void k_layer2(float* __restrict__ out,
                         const float* __restrict__ a_src2,
                         const float* __restrict__ a_dst2,
                         const float* __restrict__ b2) {
    int gtid = blockIdx.x * 256 + threadIdx.x;
    int n    = gtid >> 5;
    int lane = gtid & 31;
    if (n >= N_NODES) return;
    float asc = a_src2[0];
    float zd  = g_z[n] * a_dst2[0];
    int base = g_off[n];
    int end  = g_off[n + 1];

    float m = -1e30f, num = 0.f, den = 0.f;
    for (int t = base + lane; t < end; t += 32) {
        float zs = g_z[g_ssrc[t]];
        float v = leaky(zs * asc + zd);
        float nm = fmaxf(m, v);
        float sc = expf(m - nm);
        float w  = expf(v - nm);
        num = num * sc + w * zs;
        den = den * sc + w;
        m = nm;
    }
#pragma unroll
    for (int o = 16; o; o >>= 1) {
        float mo = __shfl_xor_sync(0xffffffffu, m, o);
        float no = __shfl_xor_sync(0xffffffffu, num, o);
        float dd = __shfl_xor_sync(0xffffffffu, den, o);
        float nm = fmaxf(m, mo);
        float s1 = expf(m - nm), s2 = expf(mo - nm);
        num = num * s1 + no * s2;
        den = den * s1 + dd * s2;
        m = nm;
    }
    if (lane == 0) {
        float v = num / (den + EPS) + b2[0];
        out[n] = 1.f / (1.f + expf(-v));
    }
}

// ---------------- launch ----------------------------------------------------
extern "C" void kernel_launch(void* const* d_in, const int* in_sizes, int n_in,
                              void* d_out, int out_size) {
    const float* x      = (const float*)d_in[0];
    const void*  ei     = d_in[1];
    const float* W1     = (const float*)d_in[2];
    const float* a_src1 = (const float*)d_in[3];
    const float* a_dst1 = (const float*)d_in[4];
    const float* b1     = (const float*)d_in[5];
    const float* W2     = (const float*)d_in[6];
    const float* a_src2 = (const float*)d_in[7];
    const float* a_dst2 = (const float*)d_in[8];
    const float* b2     = (const float*)d_in[9];
    float*       out    = (float*)d_out;

    const int TB = 256;
    int eb = (E_TOT + TB - 1) / TB;
    int ab = (N_NODES * HEADS + TB - 1) / TB;
    int wb = (N_NODES * 32 + TB - 1) / TB;
    int nb = (N_NODES + TB - 1) / TB;

    k_init<<<nb, TB>>>((const int*)ei);
    k_prep<<<eb, TB>>>(ei);
    k_scan<<<1, 1024>>>();
    k_scatter<<<eb, TB>>>();
    {
        dim3 grid((N_NODES + 127) / 128, C1 / 128);
        k_gemm1<<<grid, TB>>>(x, W1);
    }
    k_alpha1<<<ab, TB>>>(a_src1, a_dst1);
    k_agg1<<<wb, TB>>>(b1, W2);
    k_layer2<<<wb, TB>>>(out, a_src2, a_dst2, b2);
}

// round 6
// speedup vs baseline: 2.0439x; 1.1348x over previous
#include <cuda_runtime.h>
#include <cuda_bf16.h>
#include <cstdint>

#define N_NODES 50000
#define E_RAW   800000
#define E_TOT   850000   // E_RAW + N_NODES self loops
#define IN_DIM  128
#define C1      256      // HEADS*HID
#define HEADS   4
#define EPS     1e-16f

// ---------------- scratch (device globals; no allocation allowed) ----------
__device__ __align__(16) float g_h1[N_NODES * C1];
__device__ __align__(16) float g_as1[N_NODES * HEADS];
__device__ __align__(16) float g_ad1[N_NODES * HEADS];
__device__ int   g_src[E_TOT];
__device__ int   g_dst[E_TOT];
__device__ int   g_ssrc[E_TOT];    // dst-sorted src
__device__ int   g_deg[N_NODES];
__device__ int   g_cur[N_NODES];
__device__ int   g_off[N_NODES + 1];
__device__ float g_z[N_NODES];
__device__ int   g_is64;

// ---------------- helpers ---------------------------------------------------
__device__ __forceinline__ float leaky(float v) { return v > 0.f ? v : 0.2f * v; }
__device__ __forceinline__ int clampN(int v) {
    v = v < 0 ? 0 : v;
    return v >= N_NODES ? N_NODES - 1 : v;
}

// ---------------- edge prep -------------------------------------------------
__global__ void k_init(const int* __restrict__ ei32) {
    int i = blockIdx.x * 256 + threadIdx.x;
    if (i < N_NODES) { g_deg[i] = 0; g_cur[i] = 0; }
    if (blockIdx.x == 0) {
        __shared__ int ok;
        if (threadIdx.x == 0) ok = 1;
        __syncthreads();
        for (int j = threadIdx.x; j < 1024; j += 256)
            if (ei32[2 * j + 1] != 0) ok = 0;
        __syncthreads();
        if (threadIdx.x == 0) g_is64 = ok;
    }
}

__global__ void k_prep(const void* __restrict__ eiv) {
    int e = blockIdx.x * 256 + threadIdx.x;
    if (e >= E_TOT) return;
    int s, d;
    if (e < E_RAW) {
        if (g_is64) {
            const long long* ei = (const long long*)eiv;
            s = (int)ei[e];
            d = (int)ei[E_RAW + e];
        } else {
            const int* ei = (const int*)eiv;
            s = ei[e];
            d = ei[E_RAW + e];
        }
        s = clampN(s); d = clampN(d);
    } else {
        s = d = e - E_RAW;
    }
    g_src[e] = s;
    g_dst[e] = d;
    atomicAdd(&g_deg[d], 1);
}

__global__ void k_scan() {
    __shared__ int part[1024];
    const int CH = (N_NODES + 1023) / 1024;
    int t = threadIdx.x;
    int beg = t * CH;
    int fin = beg + CH; if (fin > N_NODES) fin = N_NODES;
    int s = 0;
    for (int i = beg; i < fin; i++) s += g_deg[i];
    part[t] = s;
    __syncthreads();
    for (int o = 1; o < 1024; o <<= 1) {
        int v = (t >= o) ? part[t - o] : 0;
        __syncthreads();
        part[t] += v;
        __syncthreads();
    }
    int ex = (t == 0) ? 0 : part[t - 1];
    for (int i = beg; i < fin; i++) { g_off[i] = ex; ex += g_deg[i]; }
    if (t == 1023) g_off[N_NODES] = part[1023];
}

__global__ void k_scatter() {
    int e = blockIdx.x * 256 + threadIdx.x;
    if (e >= E_TOT) return;
    int d = g_dst[e];
    int slot = g_off[d] + atomicAdd(&g_cur[d], 1);
    g_ssrc[slot] = g_src[e];
}

// ---------------- layer 1: mma.sync bf16 split GEMM --------------------------
// h1[50000,256] = x[50000,128] @ W1[128,256] in fp32 via hi/lo bf16 split:
// x*w ~= xh*wh + xh*wl + xl*wh  (3 accumulating HMMA passes).
// CTA: 512 thr (4x4 warps), tile M=128 x N=256, K=128 fully smem-resident.

#define GPITCH 68                        // words (bf16 pairs) per row, pad for banks
#define SM_AH 0                          // [128][68] u32
#define SM_AL (SM_AH + 128 * GPITCH)
#define SM_BH (SM_AL + 128 * GPITCH)     // Bt: [256 n][68] u32 (k pairs contiguous)
#define SM_BL (SM_BH + 256 * GPITCH)
#define SM_W_TOTAL (SM_BL + 256 * GPITCH)            // words
#define SM_BYTES (SM_W_TOTAL * 4)                    // 208896 bytes

__device__ __forceinline__ uint32_t pack_hi(float a, float b) {
    __nv_bfloat162 p = __floats2bfloat162_rn(a, b);
    return *(uint32_t*)&p;
}
__device__ __forceinline__ void split2(float a, float b, uint32_t& hi, uint32_t& lo) {
    __nv_bfloat16 ha = __float2bfloat16(a);
    __nv_bfloat16 hb = __float2bfloat16(b);
    __nv_bfloat16 la = __float2bfloat16(a - __bfloat162float(ha));
    __nv_bfloat16 lb = __float2bfloat16(b - __bfloat162float(hb));
    hi = (uint32_t)*(uint16_t*)&ha | ((uint32_t)*(uint16_t*)&hb << 16);
    lo = (uint32_t)*(uint16_t*)&la | ((uint32_t)*(uint16_t*)&lb << 16);
}

__device__ __forceinline__ void mma_bf16(float* c, const uint32_t* a,
                                         const uint32_t* b) {
    asm volatile(
        "mma.sync.aligned.m16n8k16.row.col.f32.bf16.bf16.f32 "
        "{%0,%1,%2,%3}, {%4,%5,%6,%7}, {%8,%9}, {%0,%1,%2,%3};"
        : "+f"(c[0]), "+f"(c[1]), "+f"(c[2]), "+f"(c[3])
        : "r"(a[0]), "r"(a[1]), "r"(a[2]), "r"(a[3]), "r"(b[0]), "r"(b[1]));
}

__global__ __launch_bounds__(512, 1) void k_gemm1_tc(const float* __restrict__ x,
                                                     const float* __restrict__ W1) {
    extern __shared__ uint32_t sm[];
    const int tid  = threadIdx.x;
    const int wid  = tid >> 5;
    const int lane = tid & 31;
    const int g    = lane >> 2;          // group id (row within fragment)
    const int tg   = lane & 3;           // thread in group (k pair)
    const int warpM = wid & 3;           // 4 -> 32 rows each
    const int warpN = wid >> 2;          // 4 -> 64 cols each
    const int row0 = blockIdx.x * 128;

    // ---- convert A: row = tid/4, k chunk = (tid%4)*32 ----
    {
        int r  = tid >> 2;
        int ks = (tid & 3) * 32;
        int row = row0 + r;
        bool valid = row < N_NODES;
        const float4* xr = (const float4*)(x + (size_t)row * IN_DIM + ks);
        uint32_t* ah = sm + SM_AH + r * GPITCH + (ks >> 1);
        uint32_t* al = sm + SM_AL + r * GPITCH + (ks >> 1);
#pragma unroll
        for (int k = 0; k < 32; k += 4) {
            float4 v = valid ? xr[k >> 2] : make_float4(0.f, 0.f, 0.f, 0.f);
            uint32_t h0, l0, h1, l1;
            split2(v.x, v.y, h0, l0);
            split2(v.z, v.w, h1, l1);
            ah[(k >> 1)] = h0; ah[(k >> 1) + 1] = h1;
            al[(k >> 1)] = l0; al[(k >> 1) + 1] = l1;
        }
    }
    // ---- convert Bt: n = tid/2, k chunk = (tid%2)*64 ----
    {
        int n  = tid >> 1;
        int ks = (tid & 1) * 64;
        uint32_t* bh = sm + SM_BH + n * GPITCH + (ks >> 1);
        uint32_t* bl = sm + SM_BL + n * GPITCH + (ks >> 1);
#pragma unroll 8
        for (int k = 0; k < 64; k += 2) {
            float w0 = W1[(size_t)(ks + k) * C1 + n];
            float w1 = W1[(size_t)(ks + k + 1) * C1 + n];
            uint32_t h, l;
            split2(w0, w1, h, l);
            bh[k >> 1] = h;
            bl[k >> 1] = l;
        }
    }
    __syncthreads();

    // ---- main MMA loops ----
    float acc[2][8][4];
#pragma unroll
    for (int i = 0; i < 2; i++)
#pragma unroll
        for (int j = 0; j < 8; j++)
#pragma unroll
            for (int q = 0; q < 4; q++) acc[i][j][q] = 0.f;

#pragma unroll
    for (int kb = 0; kb < 8; kb++) {
        int kw = kb * 8;                 // word offset of this k16 step
        uint32_t aH[2][4], aL[2][4];
#pragma unroll
        for (int ms = 0; ms < 2; ms++) {
            int r = warpM * 32 + ms * 16 + g;
            const uint32_t* pH = sm + SM_AH;
            const uint32_t* pL = sm + SM_AL;
            aH[ms][0] = pH[(r)     * GPITCH + kw + tg];
            aH[ms][1] = pH[(r + 8) * GPITCH + kw + tg];
            aH[ms][2] = pH[(r)     * GPITCH + kw + tg + 4];
            aH[ms][3] = pH[(r + 8) * GPITCH + kw + tg + 4];
            aL[ms][0] = pL[(r)     * GPITCH + kw + tg];
            aL[ms][1] = pL[(r + 8) * GPITCH + kw + tg];
            aL[ms][2] = pL[(r)     * GPITCH + kw + tg + 4];
            aL[ms][3] = pL[(r + 8) * GPITCH + kw + tg + 4];
        }
#pragma unroll
        for (int ns = 0; ns < 8; ns++) {
            int n = warpN * 64 + ns * 8 + g;
            uint32_t bH[2], bL[2];
            bH[0] = sm[SM_BH + n * GPITCH + kw + tg];
            bH[1] = sm[SM_BH + n * GPITCH + kw + tg + 4];
            bL[0] = sm[SM_BL + n * GPITCH + kw + tg];
            bL[1] = sm[SM_BL + n * GPITCH + kw + tg + 4];
#pragma unroll
            for (int ms = 0; ms < 2; ms++) {
                mma_bf16(acc[ms][ns], aH[ms], bH);
                mma_bf16(acc[ms][ns], aH[ms], bL);
                mma_bf16(acc[ms][ns], aL[ms], bH);
            }
        }
    }

    // ---- epilogue ----
#pragma unroll
    for (int ms = 0; ms < 2; ms++) {
        int r0 = row0 + warpM * 32 + ms * 16 + g;
#pragma unroll
        for (int ns = 0; ns < 8; ns++) {
            int c = warpN * 64 + ns * 8 + tg * 2;
            if (r0 < N_NODES)
                *(float2*)&g_h1[(size_t)r0 * C1 + c] =
                    make_float2(acc[ms][ns][0], acc[ms][ns][1]);
            if (r0 + 8 < N_NODES)
                *(float2*)&g_h1[(size_t)(r0 + 8) * C1 + c] =
                    make_float2(acc[ms][ns][2], acc[ms][ns][3]);
        }
    }
}

// ---------------- attention logits -------------------------------------------
__global__ void k_alpha1(const float* __restrict__ a_src1,
                         const float* __restrict__ a_dst1) {
    int t = blockIdx.x * 256 + threadIdx.x;
    if (t >= N_NODES * HEADS) return;
    int n = t >> 2, h = t & 3;
    const float4* hp  = (const float4*)(g_h1 + (size_t)n * C1 + h * 64);
    const float4* ap  = (const float4*)(a_src1 + h * 64);
    const float4* bp  = (const float4*)(a_dst1 + h * 64);
    float s = 0.f, d = 0.f;
#pragma unroll
    for (int k = 0; k < 16; k++) {
        float4 v = hp[k], a = ap[k], b = bp[k];
        s += v.x * a.x + v.y * a.y + v.z * a.z + v.w * a.w;
        d += v.x * b.x + v.y * b.y + v.z * b.z + v.w * b.w;
    }
    g_as1[t] = s;
    g_ad1[t] = d;
}

// Fused per-node: online segment softmax + weighted aggregate + relu+bias+W2.
__global__ void k_agg1(const float* __restrict__ b1, const float* __restrict__ W2) {
    int gtid = blockIdx.x * 256 + threadIdx.x;
    int n    = gtid >> 5;
    int lane = gtid & 31;
    if (n >= N_NODES) return;
    int base = g_off[n];
    int end  = g_off[n + 1];
    int head = lane >> 3;
    float4 ad4 = *(const float4*)(g_ad1 + n * 4);

    float m0 = -1e30f, m1 = -1e30f, m2 = -1e30f, m3 = -1e30f;
    float d0 = 0.f, d1 = 0.f, d2 = 0.f, d3 = 0.f;
    for (int t = base + lane; t < end; t += 32) {
        int s = g_ssrc[t];
        float4 as = *(const float4*)(g_as1 + s * 4);
        float v0 = leaky(as.x + ad4.x);
        float v1 = leaky(as.y + ad4.y);
        float v2 = leaky(as.z + ad4.z);
        float v3 = leaky(as.w + ad4.w);
        float nm;
        nm = fmaxf(m0, v0); d0 = d0 * expf(m0 - nm) + expf(v0 - nm); m0 = nm;
        nm = fmaxf(m1, v1); d1 = d1 * expf(m1 - nm) + expf(v1 - nm); m1 = nm;
        nm = fmaxf(m2, v2); d2 = d2 * expf(m2 - nm) + expf(v2 - nm); m2 = nm;
        nm = fmaxf(m3, v3); d3 = d3 * expf(m3 - nm) + expf(v3 - nm); m3 = nm;
    }
#pragma unroll
    for (int o = 16; o; o >>= 1) {
        float mo, dd, nm;
        mo = __shfl_xor_sync(0xffffffffu, m0, o); dd = __shfl_xor_sync(0xffffffffu, d0, o);
        nm = fmaxf(m0, mo); d0 = d0 * expf(m0 - nm) + dd * expf(mo - nm); m0 = nm;
        mo = __shfl_xor_sync(0xffffffffu, m1, o); dd = __shfl_xor_sync(0xffffffffu, d1, o);
        nm = fmaxf(m1, mo); d1 = d1 * expf(m1 - nm) + dd * expf(mo - nm); m1 = nm;
        mo = __shfl_xor_sync(0xffffffffu, m2, o); dd = __shfl_xor_sync(0xffffffffu, d2, o);
        nm = fmaxf(m2, mo); d2 = d2 * expf(m2 - nm) + dd * expf(mo - nm); m2 = nm;
        mo = __shfl_xor_sync(0xffffffffu, m3, o); dd = __shfl_xor_sync(0xffffffffu, d3, o);
        nm = fmaxf(m3, mo); d3 = d3 * expf(m3 - nm) + dd * expf(mo - nm); m3 = nm;
    }

    float mh  = (head == 0) ? m0 : (head == 1) ? m1 : (head == 2) ? m2 : m3;
    float dh  = (head == 0) ? d0 : (head == 1) ? d1 : (head == 2) ? d2 : d3;
    float adh = (head == 0) ? ad4.x : (head == 1) ? ad4.y : (head == 2) ? ad4.z : ad4.w;
    float inv = 1.f / (dh + EPS);

    int c0 = lane * 8;
    float4 a0 = make_float4(0.f, 0.f, 0.f, 0.f);
    float4 a1 = make_float4(0.f, 0.f, 0.f, 0.f);
    for (int t = base; t < end; t++) {
        int s = g_ssrc[t];
        float w = expf(leaky(g_as1[s * 4 + head] + adh) - mh) * inv;
        const float4* hp = (const float4*)(g_h1 + (size_t)s * C1 + c0);
        float4 v0 = hp[0];
        float4 v1 = hp[1];
        a0.x += w * v0.x; a0.y += w * v0.y; a0.z += w * v0.z; a0.w += w * v0.w;
        a1.x += w * v1.x; a1.y += w * v1.y; a1.z += w * v1.z; a1.w += w * v1.w;
    }

    float4 bb0 = *(const float4*)(b1 + c0);
    float4 bb1 = *(const float4*)(b1 + c0 + 4);
    float4 w0  = *(const float4*)(W2 + c0);
    float4 w1  = *(const float4*)(W2 + c0 + 4);
    float p = 0.f;
    p += fmaxf(a0.x + bb0.x, 0.f) * w0.x;
    p += fmaxf(a0.y + bb0.y, 0.f) * w0.y;
    p += fmaxf(a0.z + bb0.z, 0.f) * w0.z;
    p += fmaxf(a0.w + bb0.w, 0.f) * w0.w;
    p += fmaxf(a1.x + bb1.x, 0.f) * w1.x;
    p += fmaxf(a1.y + bb1.y, 0.f) * w1.y;
    p += fmaxf(a1.z + bb1.z, 0.f) * w1.z;
    p += fmaxf(a1.w + bb1.w, 0.f) * w1.w;
#pragma unroll
    for (int o = 16; o; o >>= 1) p += __shfl_xor_sync(0xffffffffu, p, o);
    if (lane == 0) g_z[n] = p;
}

// ---------------- layer 2 (fused, warp per node, online softmax) -------------
__global__ void k_layer2(float* __restrict__ out,
                         const float* __restrict__ a_src2,
                         const float* __restrict__ a_dst2,
                         const float* __restrict__ b2) {
    int gtid = blockIdx.x * 256 + threadIdx.x;
    int n    = gtid >> 5;
    int lane = gtid & 31;
    if (n >= N_NODES) return;
    float asc = a_src2[0];
    float zd  = g_z[n] * a_dst2[0];
    int base = g_off[n];
    int end  = g_off[n + 1];

    float m = -1e30f, num = 0.f, den = 0.f;
    for (int t = base + lane; t < end; t += 32) {
        float zs = g_z[g_ssrc[t]];
        float v = leaky(zs * asc + zd);
        float nm = fmaxf(m, v);
        float sc = expf(m - nm);
        float w  = expf(v - nm);
        num = num * sc + w * zs;
        den = den * sc + w;
        m = nm;
    }
#pragma unroll
    for (int o = 16; o; o >>= 1) {
        float mo = __shfl_xor_sync(0xffffffffu, m, o);
        float no = __shfl_xor_sync(0xffffffffu, num, o);
        float dd = __shfl_xor_sync(0xffffffffu, den, o);
        float nm = fmaxf(m, mo);
        float s1 = expf(m - nm), s2 = expf(mo - nm);
        num = num * s1 + no * s2;
        den = den * s1 + dd * s2;
        m = nm;
    }
    if (lane == 0) {
        float v = num / (den + EPS) + b2[0];
        out[n] = 1.f / (1.f + expf(-v));
    }
}

// ---------------- launch ----------------------------------------------------
extern "C" void kernel_launch(void* const* d_in, const int* in_sizes, int n_in,
                              void* d_out, int out_size) {
    const float* x      = (const float*)d_in[0];
    const void*  ei     = d_in[1];
    const float* W1     = (const float*)d_in[2];
    const float* a_src1 = (const float*)d_in[3];
    const float* a_dst1 = (const float*)d_in[4];
    const float* b1     = (const float*)d_in[5];
    const float* W2     = (const float*)d_in[6];
    const float* a_src2 = (const float*)d_in[7];
    const float* a_dst2 = (const float*)d_in[8];
    const float* b2     = (const float*)d_in[9];
    float*       out    = (float*)d_out;

    const int TB = 256;
    int eb = (E_TOT + TB - 1) / TB;
    int ab = (N_NODES * HEADS + TB - 1) / TB;
    int wb = (N_NODES * 32 + TB - 1) / TB;
    int nb = (N_NODES + TB - 1) / TB;

    cudaFuncSetAttribute(k_gemm1_tc, cudaFuncAttributeMaxDynamicSharedMemorySize,
                         SM_BYTES);

    k_init<<<nb, TB>>>((const int*)ei);
    k_prep<<<eb, TB>>>(ei);
    k_scan<<<1, 1024>>>();
    k_scatter<<<eb, TB>>>();
    k_gemm1_tc<<<(N_NODES + 127) / 128, 512, SM_BYTES>>>(x, W1);
    k_alpha1<<<ab, TB>>>(a_src1, a_dst1);
    k_agg1<<<wb, TB>>>(b1, W2);
    k_layer2<<<wb, TB>>>(out, a_src2, a_dst2, b2);
}